// round 7
// baseline (speedup 1.0000x reference)
#include <cuda_runtime.h>
#include <math.h>

// ---------------------------------------------------------------------------
// SpSpMM: C = A @ B, A,B sparse COO (N=4096, NNZ=131072 each), C dense fp32.
//
// R7: R5 structure (smem-accumulator spmm = proven ATOMS-floor design) with
// overheads removed:
//   0. memset node zeroes B-row counters (16 KB)
//   1. build: int4/float4 vectorized COO loads, ILP=4 bucket scatter
//   2. spmm:  PERSISTENT blocks (SMs x 8), rows strided across blocks,
//             software-pipelined row staging (prefetch next row's A bucket +
//             partner counts into registers while current row's atomics run),
//             MLP=2 inner loop, streaming float4 row store.
// ---------------------------------------------------------------------------

#define NMAX 4096
#define CAP  256           // bucket capacity (build safety)
#define SCAP 128           // staged A-entries per row; P(nA>128) ~ 0

__device__ int  g_cntB[NMAX];
__device__ int2 g_Abkt[NMAX * CAP];   // A grouped by row i   (.x=col k, .y=val)
__device__ int2 g_Bbkt[NMAX * CAP];   // B grouped by row k   (.x=col j, .y=val)
__device__ int  g_cntA[NMAX];

// ---- 1. build strided buckets (vectorized, 4 entries/thread) ---------------
__global__ void __launch_bounds__(256)
build_kernel(const int* __restrict__ a_idx,
             const float* __restrict__ a_val, int nnzA,
             const int* __restrict__ b_idx,
             const float* __restrict__ b_val, int nnzB) {
    const int quadsA = nnzA >> 2;
    const int quadsB = nnzB >> 2;
    const int tailA  = nnzA & 3;
    const int tailB  = nnzB & 3;
    int t = blockIdx.x * blockDim.x + threadIdx.x;

    if (t < quadsA) {
        int4   r = ((const int4*)a_idx)[t];
        int4   c = ((const int4*)a_idx)[quadsA + t];   // a_idx + nnzA
        float4 v = ((const float4*)a_val)[t];
        int   rr[4] = {r.x, r.y, r.z, r.w};
        int   cc[4] = {c.x, c.y, c.z, c.w};
        float vv[4] = {v.x, v.y, v.z, v.w};
        #pragma unroll
        for (int j = 0; j < 4; j++) {
            int s = atomicAdd(&g_cntA[rr[j]], 1);
            if (s < CAP)
                g_Abkt[rr[j] * CAP + s] = make_int2(cc[j], __float_as_int(vv[j]));
        }
    } else if (t < quadsA + quadsB) {
        int u = t - quadsA;
        int4   r = ((const int4*)b_idx)[u];
        int4   c = ((const int4*)b_idx)[quadsB + u];
        float4 v = ((const float4*)b_val)[u];
        int   rr[4] = {r.x, r.y, r.z, r.w};
        int   cc[4] = {c.x, c.y, c.z, c.w};
        float vv[4] = {v.x, v.y, v.z, v.w};
        #pragma unroll
        for (int j = 0; j < 4; j++) {
            int s = atomicAdd(&g_cntB[rr[j]], 1);
            if (s < CAP)
                g_Bbkt[rr[j] * CAP + s] = make_int2(cc[j], __float_as_int(vv[j]));
        }
    } else if (t < quadsA + quadsB + tailA) {
        int idx = quadsA * 4 + (t - quadsA - quadsB);
        int rr = a_idx[idx], cc = a_idx[nnzA + idx];
        int s = atomicAdd(&g_cntA[rr], 1);
        if (s < CAP)
            g_Abkt[rr * CAP + s] = make_int2(cc, __float_as_int(a_val[idx]));
    } else if (t < quadsA + quadsB + tailA + tailB) {
        int idx = quadsB * 4 + (t - quadsA - quadsB - tailA);
        int rr = b_idx[idx], cc = b_idx[nnzB + idx];
        int s = atomicAdd(&g_cntB[rr], 1);
        if (s < CAP)
            g_Bbkt[rr * CAP + s] = make_int2(cc, __float_as_int(b_val[idx]));
    }
}

// ---- 2. persistent spmm with pipelined staging ------------------------------
__global__ void __launch_bounds__(256)
spmm_row_kernel(float* __restrict__ C, int n, int stride) {
    extern __shared__ float crow[];      // n floats (16 KB @ n=4096)
    __shared__ int   sk[SCAP];           // A-entry cols (k)
    __shared__ float sv[SCAP];           // A-entry vals
    __shared__ int   sc[SCAP];           // cntB[k] prefetched
    __shared__ int   s_nA;

    const int tid  = threadIdx.x;
    const int warp = tid >> 5;
    const int lane = tid & 31;
    const int nq   = n >> 2;
    float4* crow4  = reinterpret_cast<float4*>(crow);

    // --- prefetch first row into registers ---
    int   pf_cnt = 0, pf_k = 0, pf_m = 0;
    float pf_v = 0.f;
    {
        int i = blockIdx.x;
        if (i < n) {
            pf_cnt = min(g_cntA[i], SCAP);
            if (tid < SCAP) {
                int2 p = g_Abkt[i * CAP + tid];
                pf_k = p.x;
                pf_v = __int_as_float(p.y);
                pf_m = min(g_cntB[p.x], CAP);
            }
        }
    }

    // zero accumulator once up front (kept zeroed between rows at store time)
    for (int j = tid; j < nq; j += 256)
        crow4[j] = make_float4(0.f, 0.f, 0.f, 0.f);

    for (int i = blockIdx.x; i < n; i += stride) {
        // publish prefetched staging (pure smem writes)
        if (tid == 0) s_nA = pf_cnt;
        if (tid < SCAP) {
            sk[tid] = pf_k;
            sv[tid] = pf_v;
            sc[tid] = pf_m;
        }
        __syncthreads();
        const int nA = s_nA;

        // kick prefetch for the NEXT row (long-latency loads hidden under
        // this row's atomics)
        {
            int i2 = i + stride;
            if (i2 < n) {
                pf_cnt = min(g_cntA[i2], SCAP);
                if (tid < SCAP) {
                    int2 p = g_Abkt[i2 * CAP + tid];
                    pf_k = p.x;
                    pf_v = __int_as_float(p.y);
                    pf_m = min(g_cntB[p.x], CAP);
                }
            }
        }

        // warp handles A-entries e and e+8 together (MLP=2)
        for (int e = warp; e < nA; e += 16) {
            const int  e2   = e + 8;
            const bool has2 = (e2 < nA);
            const int   k1 = sk[e];
            const float a1 = sv[e];
            const int   m1 = sc[e];
            const int   k2 = has2 ? sk[e2] : 0;
            const float a2 = has2 ? sv[e2] : 0.f;
            const int   m2 = has2 ? sc[e2] : 0;
            const int   mm = m1 > m2 ? m1 : m2;

            for (int t = lane; t < mm; t += 32) {
                int2 q1, q2;
                const bool l1 = (t < m1);
                const bool l2 = (t < m2);
                if (l1) q1 = g_Bbkt[k1 * CAP + t];
                if (l2) q2 = g_Bbkt[k2 * CAP + t];
                if (l1) atomicAdd(&crow[q1.x], a1 * __int_as_float(q1.y));
                if (l2) atomicAdd(&crow[q2.x], a2 * __int_as_float(q2.y));
            }
        }
        __syncthreads();

        // streaming row store + re-zero (same thread touches same address:
        // no intra-pair race; cross-warp ordering handled by the barriers)
        float4* out4 = reinterpret_cast<float4*>(C + (size_t)i * n);
        const float4 z = make_float4(0.f, 0.f, 0.f, 0.f);
        for (int j = tid; j < nq; j += 256) {
            out4[j]  = crow4[j];
            crow4[j] = z;
        }
        __syncthreads();
    }
}

// ---------------------------------------------------------------------------
extern "C" void kernel_launch(void* const* d_in, const int* in_sizes, int n_in,
                              void* d_out, int out_size) {
    const int*   a_idx = (const int*)  d_in[0];
    const float* a_val = (const float*)d_in[1];
    const int*   b_idx = (const int*)  d_in[2];
    const float* b_val = (const float*)d_in[3];
    float*       C     = (float*)d_out;

    const int nnzA = in_sizes[1];
    const int nnzB = in_sizes[3];
    const int n    = (int)(sqrt((double)out_size) + 0.5);

    // 0. zero counters (both arrays are adjacent declarations; zero each)
    void* p = nullptr;
    cudaGetSymbolAddress(&p, g_cntB);
    cudaMemsetAsync(p, 0, NMAX * sizeof(int));
    cudaGetSymbolAddress(&p, g_cntA);
    cudaMemsetAsync(p, 0, NMAX * sizeof(int));

    // 1. build buckets
    {
        int items   = (nnzA >> 2) + (nnzB >> 2) + (nnzA & 3) + (nnzB & 3);
        int blocks  = (items + 255) / 256;
        build_kernel<<<blocks, 256>>>(a_idx, a_val, nnzA, b_idx, b_val, nnzB);
    }

    // 2. persistent spmm
    {
        int dev = 0, sms = 0;
        cudaGetDevice(&dev);
        cudaDeviceGetAttribute(&sms, cudaDevAttrMultiProcessorCount, dev);
        if (sms <= 0) sms = 148;
        int blocks = sms * 8;
        if (blocks > n) blocks = n;
        size_t smem = (size_t)n * sizeof(float);
        spmm_row_kernel<<<blocks, 256, smem>>>(C, n, blocks);
    }
}

// round 8
// speedup vs baseline: 1.2786x; 1.2786x over previous
#include <cuda_runtime.h>
#include <math.h>

// ---------------------------------------------------------------------------
// SpSpMM: C = A @ B, A,B sparse COO (N=4096, NNZ=131072 each), C dense fp32.
//
// R8: hybrid scatter. Rows i%3==0 scatter products straight into pre-zeroed C
// via red.global.add.f32 (L2 atomic ALU path); other rows use the proven
// smem-accumulator ATOMS path (R5, 32 regs, 8 blocks/SM). Interleaved by row
// index so every wave mixes both paths: REDG blocks idle on memory while
// ATOMS blocks saturate the per-SM LSU smem-atomic port.
//   0. memset node: counters (32 KB, one contiguous array)
//   1. build: vectorized bucket build  +  zero C rows of the REDG set
//   2. spmm: one block per row, path chosen by i%3
// ---------------------------------------------------------------------------

#define NMAX 4096
#define CAP  256           // bucket capacity; Poisson(32) tail => never hit
#define RMOD 3             // rows with i%RMOD==0 take the REDG path

__device__ int  g_cnt[2 * NMAX];      // [0,NMAX)=A rows, [NMAX,2N)=B rows
__device__ int2 g_Abkt[NMAX * CAP];   // .x = col k, .y = bits(val)
__device__ int2 g_Bbkt[NMAX * CAP];   // .x = col j, .y = bits(val)

__device__ __forceinline__ void red_add_f32(float* p, float v) {
    asm volatile("red.global.add.f32 [%0], %1;" :: "l"(p), "f"(v) : "memory");
}

// ---- 1. build buckets + zero REDG-rows of C --------------------------------
__global__ void __launch_bounds__(256)
build_zero_kernel(const int* __restrict__ a_idx,
                  const float* __restrict__ a_val, int nnzA,
                  const int* __restrict__ b_idx,
                  const float* __restrict__ b_val, int nnzB,
                  float* __restrict__ C, int n, int zb) {
    const int tid = threadIdx.x;

    if (blockIdx.x < zb) {
        // zero C rows i%RMOD==0 (the REDG target region)
        const int nR = (n + RMOD - 1) / RMOD;
        const int nq = n >> 2;
        const float4 z = make_float4(0.f, 0.f, 0.f, 0.f);
        for (int r = blockIdx.x; r < nR; r += zb) {
            float4* row4 = reinterpret_cast<float4*>(C + (size_t)(r * RMOD) * n);
            for (int j = tid; j < nq; j += 256)
                row4[j] = z;
        }
        return;
    }

    const int quadsA = nnzA >> 2;
    const int quadsB = nnzB >> 2;
    const int tailA  = nnzA & 3;
    const int tailB  = nnzB & 3;
    int t = (blockIdx.x - zb) * 256 + tid;

    if (t < quadsA) {
        int4   r = ((const int4*)a_idx)[t];
        int4   c = ((const int4*)a_idx)[quadsA + t];   // a_idx + nnzA
        float4 v = ((const float4*)a_val)[t];
        int   rr[4] = {r.x, r.y, r.z, r.w};
        int   cc[4] = {c.x, c.y, c.z, c.w};
        float vv[4] = {v.x, v.y, v.z, v.w};
        #pragma unroll
        for (int j = 0; j < 4; j++) {
            int s = atomicAdd(&g_cnt[rr[j]], 1);
            if (s < CAP)
                g_Abkt[rr[j] * CAP + s] = make_int2(cc[j], __float_as_int(vv[j]));
        }
    } else if (t < quadsA + quadsB) {
        int u = t - quadsA;
        int4   r = ((const int4*)b_idx)[u];
        int4   c = ((const int4*)b_idx)[quadsB + u];
        float4 v = ((const float4*)b_val)[u];
        int   rr[4] = {r.x, r.y, r.z, r.w};
        int   cc[4] = {c.x, c.y, c.z, c.w};
        float vv[4] = {v.x, v.y, v.z, v.w};
        #pragma unroll
        for (int j = 0; j < 4; j++) {
            int s = atomicAdd(&g_cnt[NMAX + rr[j]], 1);
            if (s < CAP)
                g_Bbkt[rr[j] * CAP + s] = make_int2(cc[j], __float_as_int(vv[j]));
        }
    } else if (t < quadsA + quadsB + tailA) {
        int idx = quadsA * 4 + (t - quadsA - quadsB);
        int rr = a_idx[idx], cc = a_idx[nnzA + idx];
        int s = atomicAdd(&g_cnt[rr], 1);
        if (s < CAP)
            g_Abkt[rr * CAP + s] = make_int2(cc, __float_as_int(a_val[idx]));
    } else if (t < quadsA + quadsB + tailA + tailB) {
        int idx = quadsB * 4 + (t - quadsA - quadsB - tailA);
        int rr = b_idx[idx], cc = b_idx[nnzB + idx];
        int s = atomicAdd(&g_cnt[NMAX + rr], 1);
        if (s < CAP)
            g_Bbkt[rr * CAP + s] = make_int2(cc, __float_as_int(b_val[idx]));
    }
}

// ---- 2. hybrid spmm: one block per row -------------------------------------
__global__ void __launch_bounds__(256)
spmm_hybrid_kernel(float* __restrict__ C, int n) {
    extern __shared__ float crow[];      // n floats (ATOMS path only)
    __shared__ int   sk[CAP];            // A-entry cols (k)
    __shared__ float sv[CAP];            // A-entry vals
    __shared__ int   sc[CAP];            // cntB[k] prefetched

    const int i    = blockIdx.x;
    const int tid  = threadIdx.x;
    const int warp = tid >> 5;
    const int lane = tid & 31;
    const int nq   = n >> 2;
    const bool redg_path = (i % RMOD) == 0;

    float4* crow4 = reinterpret_cast<float4*>(crow);
    if (!redg_path) {
        // zero row accumulator (overlaps the staging loads below)
        for (int j = tid; j < nq; j += 256)
            crow4[j] = make_float4(0.f, 0.f, 0.f, 0.f);
    }

    // stage this row's A bucket + partner counts in one parallel round
    const int nA = min(g_cnt[i], CAP);
    if (tid < nA) {
        int2 p = g_Abkt[i * CAP + tid];
        sk[tid] = p.x;
        sv[tid] = __int_as_float(p.y);
        sc[tid] = min(g_cnt[NMAX + p.x], CAP);
    }
    __syncthreads();

    if (redg_path) {
        // scatter products straight into (pre-zeroed) C row via L2 atomics
        float* row = C + (size_t)i * n;
        for (int e = warp; e < nA; e += 16) {
            const int  e2   = e + 8;
            const bool has2 = (e2 < nA);
            const int   k1 = sk[e];
            const float a1 = sv[e];
            const int   m1 = sc[e];
            const int   k2 = has2 ? sk[e2] : 0;
            const float a2 = has2 ? sv[e2] : 0.f;
            const int   m2 = has2 ? sc[e2] : 0;
            const int   mm = m1 > m2 ? m1 : m2;

            for (int t = lane; t < mm; t += 32) {
                int2 q1, q2;
                const bool l1 = (t < m1);
                const bool l2 = (t < m2);
                if (l1) q1 = g_Bbkt[k1 * CAP + t];
                if (l2) q2 = g_Bbkt[k2 * CAP + t];
                if (l1) red_add_f32(row + q1.x, a1 * __int_as_float(q1.y));
                if (l2) red_add_f32(row + q2.x, a2 * __int_as_float(q2.y));
            }
        }
        return;
    }

    // ATOMS path: accumulate in shared memory (MLP=2), then stream the row out
    for (int e = warp; e < nA; e += 16) {
        const int  e2   = e + 8;
        const bool has2 = (e2 < nA);
        const int   k1 = sk[e];
        const float a1 = sv[e];
        const int   m1 = sc[e];
        const int   k2 = has2 ? sk[e2] : 0;
        const float a2 = has2 ? sv[e2] : 0.f;
        const int   m2 = has2 ? sc[e2] : 0;
        const int   mm = m1 > m2 ? m1 : m2;

        for (int t = lane; t < mm; t += 32) {
            int2 q1, q2;
            const bool l1 = (t < m1);
            const bool l2 = (t < m2);
            if (l1) q1 = g_Bbkt[k1 * CAP + t];
            if (l2) q2 = g_Bbkt[k2 * CAP + t];
            if (l1) atomicAdd(&crow[q1.x], a1 * __int_as_float(q1.y));
            if (l2) atomicAdd(&crow[q2.x], a2 * __int_as_float(q2.y));
        }
    }
    __syncthreads();

    float4* out4 = reinterpret_cast<float4*>(C + (size_t)i * n);
    for (int j = tid; j < nq; j += 256)
        out4[j] = crow4[j];
}

// ---------------------------------------------------------------------------
extern "C" void kernel_launch(void* const* d_in, const int* in_sizes, int n_in,
                              void* d_out, int out_size) {
    const int*   a_idx = (const int*)  d_in[0];
    const float* a_val = (const float*)d_in[1];
    const int*   b_idx = (const int*)  d_in[2];
    const float* b_val = (const float*)d_in[3];
    float*       C     = (float*)d_out;

    const int nnzA = in_sizes[1];
    const int nnzB = in_sizes[3];
    const int n    = (int)(sqrt((double)out_size) + 0.5);

    // 0. zero counters (single contiguous memset node)
    void* cnt_ptr = nullptr;
    cudaGetSymbolAddress(&cnt_ptr, g_cnt);
    cudaMemsetAsync(cnt_ptr, 0, 2 * NMAX * sizeof(int));

    // 1. build buckets + zero REDG rows of C
    {
        const int zb     = 512;
        const int items  = (nnzA >> 2) + (nnzB >> 2) + (nnzA & 3) + (nnzB & 3);
        const int bb     = (items + 255) / 256;
        build_zero_kernel<<<zb + bb, 256>>>(a_idx, a_val, nnzA,
                                            b_idx, b_val, nnzB, C, n, zb);
    }

    // 2. hybrid spmm (one block per row)
    {
        size_t smem = (size_t)n * sizeof(float);
        spmm_hybrid_kernel<<<n, 256, smem>>>(C, n);
    }
}